// round 7
// baseline (speedup 1.0000x reference)
#include <cuda_runtime.h>
#include <cuda_bf16.h>
#include <cstdint>

#define NPROMPT 20

// Fallback-path scratch.
__device__ unsigned long long g_src[1 << 16];

// ===========================================================================
// prep_patch_kernel: one block per batch row (L <= 1024).
//  - probes sid dtype (int32 vs int64) in-kernel
//  - ballot-scans pad ranks, writes mask output
//  - overwrites the <=NPROMPT take-rows of `out` with prompt rows
// Runs AFTER the bulk memcpy, so its writes win.
// ===========================================================================
__global__ void prep_patch_kernel(const int* __restrict__ mask,
                                  const float4* __restrict__ prompts,
                                  const void* __restrict__ sid_raw,
                                  float4* __restrict__ out,
                                  float* __restrict__ mask_out,
                                  int B, int L, int Dv, long long NS) {
    int b = blockIdx.x;
    int t = threadIdx.x;

    // sid dtype probe: buffer is int64 iff all odd 32-bit words among the
    // first B words are zero (ids < 2^31). In-bounds for both layouts.
    const int* sw = (const int*)sid_raw;
    int all0 = 1;
    for (int i = 1; i < B; i += 2)
        if (sw[i] != 0) { all0 = 0; break; }
    long long s = all0 ? ((const long long*)sid_raw)[b] : (long long)sw[b];
    if (s < 0) s = 0;
    if (s >= NS) s = NS - 1;

    int m = 0, pad = 0;
    if (t < L) {
        m = mask[(size_t)b * L + t];
        pad = (m == 0);
    }
    unsigned bal = __ballot_sync(0xFFFFFFFFu, pad);
    int lane = t & 31;
    int warp = t >> 5;

    __shared__ int wtot[32];
    __shared__ int taken[NPROMPT];   // taken[r] = l-position with rank r
    __shared__ int ntake_sh;
    if (t == 0) ntake_sh = 0;
    if (lane == 0) wtot[warp] = __popc(bal);
    __syncthreads();

    int prefix = 0;
    for (int w = 0; w < warp; ++w) prefix += wtot[w];
    int rank = prefix + __popc(bal & ((1u << lane) - 1u));

    if (t < L) {
        int take = (pad && rank < NPROMPT);
        if (take) {
            taken[rank] = t;
            atomicAdd(&ntake_sh, 1);
        }
        if (mask_out) mask_out[(size_t)b * L + t] = take ? 1.0f : (float)m;
    }
    __syncthreads();

    int ntake = ntake_sh;
    if (ntake == 0) return;

    // Cooperative overwrite: ntake rows x Dv float4s.
    const float4* pbase = prompts + (size_t)s * NPROMPT * Dv;
    int n = ntake * Dv;
    for (int i = t; i < n; i += blockDim.x) {
        int r = i / Dv;
        int c = i - r * Dv;
        int l = taken[r];
        out[((size_t)b * L + l) * Dv + c] = pbase[(size_t)r * Dv + c];
    }
}

// ===========================================================================
// Fallback path (unexpected shapes): resolved-pointer prep + per-warp copy.
// ===========================================================================
__global__ void prep_serial_kernel(const int* __restrict__ mask,
                                   const float* __restrict__ in,
                                   const float* __restrict__ prompts,
                                   const void* __restrict__ sid_raw,
                                   float* __restrict__ mask_out,
                                   int B, int L, int D, long long NS) {
    int b = blockIdx.x * blockDim.x + threadIdx.x;
    if (b >= B) return;
    const int* sw = (const int*)sid_raw;
    int all0 = 1;
    for (int i = 1; i < B; i += 2)
        if (sw[i] != 0) { all0 = 0; break; }
    long long s = all0 ? ((const long long*)sid_raw)[b] : (long long)sw[b];
    if (s < 0) s = 0;
    if (s >= NS) s = NS - 1;
    int cnt = 0;
    for (int l = 0; l < L; ++l) {
        size_t row = (size_t)b * L + l;
        int m = mask[row];
        int pad = (m == 0);
        int take = pad && (cnt < NPROMPT);
        const float* src = take
            ? prompts + ((size_t)s * NPROMPT + cnt) * (size_t)D
            : in + row * (size_t)D;
        g_src[row] = (unsigned long long)src;
        if (mask_out) mask_out[row] = take ? 1.0f : (float)m;
        cnt += pad;
    }
}

__global__ void copy_scalar_kernel(float* __restrict__ out, int BL, int D) {
    int row = blockIdx.x;
    if (row >= BL) return;
    const float* __restrict__ src = (const float*)g_src[row];
    float* __restrict__ dst = out + (size_t)row * D;
    for (int c = threadIdx.x; c < D; c += blockDim.x) dst[c] = src[c];
}

// ===========================================================================
extern "C" void kernel_launch(void* const* d_in, const int* in_sizes, int n_in,
                              void* d_out, int out_size) {
    // Bind inputs by size rank:
    //   smallest     -> sample_id_tensor [B]
    //   2nd smallest -> attention_mask   [B*L]
    //   2nd largest  -> input_embeds     [B*L*D]
    //   largest      -> prompt_embeddings [NS*NPROMPT*D]
    int idx[4] = {0, 1, 2, 3};
    for (int i = 0; i < 4; ++i)
        for (int j = i + 1; j < 4; ++j)
            if (in_sizes[idx[j]] < in_sizes[idx[i]]) {
                int t = idx[i]; idx[i] = idx[j]; idx[j] = t;
            }
    const void*  sid     = d_in[idx[0]];
    const int*   mask    = (const int*)d_in[idx[1]];
    const float* embeds  = (const float*)d_in[idx[2]];
    const float* prompts = (const float*)d_in[idx[3]];

    int B  = in_sizes[idx[0]];
    int BL = in_sizes[idx[1]];
    int L  = BL / B;
    long long D  = (long long)in_sizes[idx[2]] / BL;
    long long NS = (long long)in_sizes[idx[3]] / (NPROMPT * D);

    float* out = (float*)d_out;
    size_t embed_elems = (size_t)BL * (size_t)D;
    float* mask_out = ((size_t)out_size >= embed_elems + (size_t)BL)
                          ? out + embed_elems
                          : nullptr;

    if (L <= 1024 && (D & 3) == 0) {
        // --- Node 1: bulk flat copy of input_embeds -> out ---
        cudaMemcpyAsync(out, embeds, embed_elems * sizeof(float),
                        cudaMemcpyDeviceToDevice, 0);
        // --- Node 2: rank scan + mask + prompt-row overwrite ---
        int threads = ((L + 31) / 32) * 32;
        if (threads < 128) threads = 128;
        prep_patch_kernel<<<B, threads>>>(
            mask, (const float4*)prompts, sid, (float4*)out, mask_out,
            B, L, (int)(D >> 2), NS);
    } else {
        // Fallback: resolved-pointer prep + per-row copy.
        int threads = 128;
        int blocks = (B + threads - 1) / threads;
        prep_serial_kernel<<<blocks, threads>>>(mask, embeds, prompts, sid,
                                                mask_out, B, (int)L, (int)D, NS);
        int cthreads = (int)(D < 1024 ? ((D + 31) / 32) * 32 : 1024);
        copy_scalar_kernel<<<BL, cthreads>>>(out, BL, (int)D);
    }
}

// round 8
// speedup vs baseline: 1.2073x; 1.2073x over previous
#include <cuda_runtime.h>
#include <cuda_bf16.h>
#include <cstdint>

#define NPROMPT 20

// Patch table: for (b, r) slot, target l-position in row b, or -1.
__device__ int g_patch[4096 * NPROMPT];
// Resolved sample id per batch row.
__device__ long long g_sid[4096];
// Fallback-path scratch.
__device__ unsigned long long g_src[1 << 16];

// ===========================================================================
// Kernel A: prep. One block per batch row (L <= 1024).
//  - probe sid dtype (int32 vs int64)
//  - ballot-scan pad ranks, write mask output
//  - emit compact patch table
// ===========================================================================
__global__ void prep_kernel(const int* __restrict__ mask,
                            const void* __restrict__ sid_raw,
                            float* __restrict__ mask_out,
                            int B, int L, long long NS) {
    int b = blockIdx.x;
    int t = threadIdx.x;

    // sid dtype probe: int64 iff all odd 32-bit words among the first B words
    // are zero (ids < 2^31). Reading B words is in-bounds for both layouts.
    const int* sw = (const int*)sid_raw;
    int all0 = 1;
    for (int i = 1; i < B; i += 2)
        if (sw[i] != 0) { all0 = 0; break; }
    long long s = all0 ? ((const long long*)sid_raw)[b] : (long long)sw[b];
    if (s < 0) s = 0;
    if (s >= NS) s = NS - 1;
    if (t == 0) g_sid[b] = s;

    // init patch slots to -1
    if (t < NPROMPT) g_patch[b * NPROMPT + t] = -1;

    int m = 0, pad = 0;
    if (t < L) {
        m = mask[(size_t)b * L + t];
        pad = (m == 0);
    }
    unsigned bal = __ballot_sync(0xFFFFFFFFu, pad);
    int lane = t & 31;
    int warp = t >> 5;

    __shared__ int wtot[32];
    if (lane == 0) wtot[warp] = __popc(bal);
    __syncthreads();

    int prefix = 0;
    for (int w = 0; w < warp; ++w) prefix += wtot[w];
    int rank = prefix + __popc(bal & ((1u << lane) - 1u));

    if (t < L) {
        int take = (pad && rank < NPROMPT);
        if (take) g_patch[b * NPROMPT + rank] = t;
        if (mask_out) mask_out[(size_t)b * L + t] = take ? 1.0f : (float)m;
    }
}

// ===========================================================================
// Kernel B: pure flat streaming copy, zero indirection.
// Grid-stride, 4 strided float4s per thread per outer iteration (MLP=4).
// ===========================================================================
__global__ void __launch_bounds__(256) flat_copy_kernel(
    const float4* __restrict__ in, float4* __restrict__ out, size_t n) {
    size_t stride = (size_t)gridDim.x * blockDim.x;
    size_t i = (size_t)blockIdx.x * blockDim.x + threadIdx.x;
    for (; i + 3 * stride < n; i += 4 * stride) {
        float4 a = in[i];
        float4 b = in[i + stride];
        float4 c = in[i + 2 * stride];
        float4 d = in[i + 3 * stride];
        out[i] = a;
        out[i + stride] = b;
        out[i + 2 * stride] = c;
        out[i + 3 * stride] = d;
    }
    for (; i < n; i += stride) out[i] = in[i];
}

// ===========================================================================
// Kernel C: patch. One block per (b, rank) slot; copies one prompt row
// over the bulk-copied output. Runs after Kernel B in stream order.
// ===========================================================================
__global__ void patch_kernel(const float4* __restrict__ prompts,
                             float4* __restrict__ out,
                             int L, int Dv) {
    int slot = blockIdx.x;               // b * NPROMPT + r
    int l = g_patch[slot];
    if (l < 0) return;
    int b = slot / NPROMPT;
    int r = slot - b * NPROMPT;
    long long s = g_sid[b];

    const float4* src = prompts + ((size_t)s * NPROMPT + r) * Dv;
    float4* dst = out + ((size_t)b * L + l) * Dv;
    for (int c = threadIdx.x; c < Dv; c += blockDim.x) dst[c] = src[c];
}

// ===========================================================================
// Fallback path (unexpected shapes).
// ===========================================================================
__global__ void prep_serial_kernel(const int* __restrict__ mask,
                                   const float* __restrict__ in,
                                   const float* __restrict__ prompts,
                                   const void* __restrict__ sid_raw,
                                   float* __restrict__ mask_out,
                                   int B, int L, int D, long long NS) {
    int b = blockIdx.x * blockDim.x + threadIdx.x;
    if (b >= B) return;
    const int* sw = (const int*)sid_raw;
    int all0 = 1;
    for (int i = 1; i < B; i += 2)
        if (sw[i] != 0) { all0 = 0; break; }
    long long s = all0 ? ((const long long*)sid_raw)[b] : (long long)sw[b];
    if (s < 0) s = 0;
    if (s >= NS) s = NS - 1;
    int cnt = 0;
    for (int l = 0; l < L; ++l) {
        size_t row = (size_t)b * L + l;
        int m = mask[row];
        int pad = (m == 0);
        int take = pad && (cnt < NPROMPT);
        const float* src = take
            ? prompts + ((size_t)s * NPROMPT + cnt) * (size_t)D
            : in + row * (size_t)D;
        g_src[row] = (unsigned long long)src;
        if (mask_out) mask_out[row] = take ? 1.0f : (float)m;
        cnt += pad;
    }
}

__global__ void copy_scalar_kernel(float* __restrict__ out, int BL, int D) {
    int row = blockIdx.x;
    if (row >= BL) return;
    const float* __restrict__ src = (const float*)g_src[row];
    float* __restrict__ dst = out + (size_t)row * D;
    for (int c = threadIdx.x; c < D; c += blockDim.x) dst[c] = src[c];
}

// ===========================================================================
extern "C" void kernel_launch(void* const* d_in, const int* in_sizes, int n_in,
                              void* d_out, int out_size) {
    // Bind inputs by size rank:
    //   smallest     -> sample_id_tensor [B]
    //   2nd smallest -> attention_mask   [B*L]
    //   2nd largest  -> input_embeds     [B*L*D]
    //   largest      -> prompt_embeddings [NS*NPROMPT*D]
    int idx[4] = {0, 1, 2, 3};
    for (int i = 0; i < 4; ++i)
        for (int j = i + 1; j < 4; ++j)
            if (in_sizes[idx[j]] < in_sizes[idx[i]]) {
                int t = idx[i]; idx[i] = idx[j]; idx[j] = t;
            }
    const void*  sid     = d_in[idx[0]];
    const int*   mask    = (const int*)d_in[idx[1]];
    const float* embeds  = (const float*)d_in[idx[2]];
    const float* prompts = (const float*)d_in[idx[3]];

    int B  = in_sizes[idx[0]];
    int BL = in_sizes[idx[1]];
    int L  = BL / B;
    long long D  = (long long)in_sizes[idx[2]] / BL;
    long long NS = (long long)in_sizes[idx[3]] / (NPROMPT * D);

    float* out = (float*)d_out;
    size_t embed_elems = (size_t)BL * (size_t)D;
    float* mask_out = ((size_t)out_size >= embed_elems + (size_t)BL)
                          ? out + embed_elems
                          : nullptr;

    if (L <= 1024 && (D & 3) == 0 && B <= 4096) {
        int Dv = (int)(D >> 2);

        // --- A: prep (ranks, mask, patch table) ---
        int athreads = ((L + 31) / 32) * 32;
        if (athreads < 128) athreads = 128;
        prep_kernel<<<B, athreads>>>(mask, sid, mask_out, B, L, NS);

        // --- B: flat bulk copy ---
        size_t n4 = embed_elems >> 2;
        int bthreads = 256;
        int bblocks = (int)((n4 + (size_t)bthreads * 4 - 1) / ((size_t)bthreads * 4));
        flat_copy_kernel<<<bblocks, bthreads>>>(
            (const float4*)embeds, (float4*)out, n4);

        // --- C: patch prompt rows over output ---
        int cthreads = Dv < 1024 ? ((Dv + 31) / 32) * 32 : 1024;
        if (cthreads < 64) cthreads = 64;
        patch_kernel<<<B * NPROMPT, cthreads>>>(
            (const float4*)prompts, (float4*)out, L, Dv);
    } else {
        // Fallback: resolved-pointer prep + per-row copy.
        int threads = 128;
        int blocks = (B + threads - 1) / threads;
        prep_serial_kernel<<<blocks, threads>>>(mask, embeds, prompts, sid,
                                                mask_out, B, (int)L, (int)D, NS);
        int cthreads = (int)(D < 1024 ? ((D + 31) / 32) * 32 : 1024);
        copy_scalar_kernel<<<BL, cthreads>>>(out, BL, (int)D);
    }
}

// round 10
// speedup vs baseline: 1.2110x; 1.0031x over previous
#include <cuda_runtime.h>
#include <cuda_bf16.h>
#include <cstdint>

#define NPROMPT 20

// Prep outputs (written by K1, read by K2):
__device__ int g_patch[4096 * NPROMPT];        // (b,r) -> l position or -1
__device__ long long g_sid[4096];              // resolved sample id per b
__device__ unsigned g_skipw[(1 << 16) / 4];    // packed skip bytes, 4 rows/word
// Fallback-path scratch.
__device__ unsigned long long g_src[1 << 16];

// ===========================================================================
// K1: prep. One block per batch row (L <= 1024, L % 4 == 0).
// Parallel sid dtype probe + ballot rank scan + mask out + patch table +
// packed skip flags.
// ===========================================================================
__global__ void prep_kernel(const int* __restrict__ mask,
                            const void* __restrict__ sid_raw,
                            float* __restrict__ mask_out,
                            int B, int L, long long NS) {
    int b = blockIdx.x;
    int t = threadIdx.x;
    int lane = t & 31;
    int warp = t >> 5;

    __shared__ int s_all0;
    __shared__ int wtot[32];
    extern __shared__ unsigned char s_take[];   // L bytes

    // --- parallel dtype probe: int64 iff all odd words of first B words are 0
    if (t == 0) s_all0 = 1;
    __syncthreads();
    const int* sw = (const int*)sid_raw;
    if (t < B && (t & 1) && sw[t] != 0) s_all0 = 0;   // benign race, write-0 only
    __syncthreads();
    long long s = s_all0 ? ((const long long*)sid_raw)[b] : (long long)sw[b];
    if (s < 0) s = 0;
    if (s >= NS) s = NS - 1;
    if (t == 0) g_sid[b] = s;
    if (t < NPROMPT) g_patch[b * NPROMPT + t] = -1;

    // --- ballot rank scan ---
    int m = 0, pad = 0;
    if (t < L) {
        m = mask[(size_t)b * L + t];
        pad = (m == 0);
    }
    unsigned bal = __ballot_sync(0xFFFFFFFFu, pad);
    if (lane == 0) wtot[warp] = __popc(bal);
    __syncthreads();
    int prefix = 0;
    for (int w = 0; w < warp; ++w) prefix += wtot[w];
    int rank = prefix + __popc(bal & ((1u << lane) - 1u));

    if (t < L) {
        int take = (pad && rank < NPROMPT);
        s_take[t] = (unsigned char)take;
        if (take) g_patch[b * NPROMPT + rank] = t;
        if (mask_out) mask_out[(size_t)b * L + t] = take ? 1.0f : (float)m;
    }
    __syncthreads();

    // --- pack skip flags: one word per 4 rows ---
    int nw = L >> 2;
    for (int q = t; q < nw; q += blockDim.x) {
        unsigned w0 = s_take[q * 4 + 0];
        unsigned w1 = s_take[q * 4 + 1];
        unsigned w2 = s_take[q * 4 + 2];
        unsigned w3 = s_take[q * 4 + 3];
        g_skipw[(size_t)b * nw + q] = w0 | (w1 << 8) | (w2 << 16) | (w3 << 24);
    }
}

// ===========================================================================
// K2: mega kernel. Blocks [0, npatch): patch prompt rows into out.
//     Blocks [npatch, npatch+ncopy): flat copy 4 rows (768 float4s) each,
//     stores predicated off for patched rows. Disjoint writes -> race-free.
// DV = float4s per row (templated, 192 for D=768).
// ===========================================================================
template <int DV>
__global__ void __launch_bounds__(256) mega_kernel(
    const float4* __restrict__ in,
    const float4* __restrict__ prompts,
    float4* __restrict__ out,
    int L, int npatch) {
    int t = threadIdx.x;

    if (blockIdx.x < (unsigned)npatch) {
        // ---- PATCH role ----
        int slot = blockIdx.x;
        int l = g_patch[slot];
        if (l < 0) return;
        int b = slot / NPROMPT;
        int r = slot - b * NPROMPT;
        long long s = g_sid[b];
        const float4* src = prompts + ((size_t)s * NPROMPT + r) * DV;
        float4* dst = out + ((size_t)b * L + l) * DV;
        for (int c = t; c < DV; c += blockDim.x) dst[c] = src[c];
        return;
    }

    // ---- COPY role: 4 rows = 4*DV float4s per block ----
    int cb = blockIdx.x - npatch;
    unsigned f = g_skipw[cb];                       // independent flag load
    size_t base = (size_t)cb * (4 * DV);

    int j0 = t, j1 = t + 256, j2 = t + 512;         // 4*192 = 768 = 3*256
    float4 v0 = in[base + j0];
    float4 v1 = in[base + j1];
    float4 v2 = in[base + j2];
    if (!((f >> (8 * (j0 / DV))) & 1u)) out[base + j0] = v0;
    if (!((f >> (8 * (j1 / DV))) & 1u)) out[base + j1] = v1;
    if (!((f >> (8 * (j2 / DV))) & 1u)) out[base + j2] = v2;
}

// ===========================================================================
// Generic path (Dv != 192): separate flat copy + patch (proven R7 shape),
// with the fixed fast prep.
// ===========================================================================
__global__ void __launch_bounds__(256) flat_copy_kernel(
    const float4* __restrict__ in, float4* __restrict__ out, size_t n) {
    size_t stride = (size_t)gridDim.x * blockDim.x;
    size_t i = (size_t)blockIdx.x * blockDim.x + threadIdx.x;
    for (; i + 3 * stride < n; i += 4 * stride) {
        float4 a = in[i], b = in[i + stride];
        float4 c = in[i + 2 * stride], d = in[i + 3 * stride];
        out[i] = a; out[i + stride] = b;
        out[i + 2 * stride] = c; out[i + 3 * stride] = d;
    }
    for (; i < n; i += stride) out[i] = in[i];
}

__global__ void patch_kernel(const float4* __restrict__ prompts,
                             float4* __restrict__ out, int L, int Dv) {
    int slot = blockIdx.x;
    int l = g_patch[slot];
    if (l < 0) return;
    int b = slot / NPROMPT;
    int r = slot - b * NPROMPT;
    long long s = g_sid[b];
    const float4* src = prompts + ((size_t)s * NPROMPT + r) * Dv;
    float4* dst = out + ((size_t)b * L + l) * Dv;
    for (int c = threadIdx.x; c < Dv; c += blockDim.x) dst[c] = src[c];
}

// ===========================================================================
// Fallback path (unexpected shapes).
// ===========================================================================
__global__ void prep_serial_kernel(const int* __restrict__ mask,
                                   const float* __restrict__ in,
                                   const float* __restrict__ prompts,
                                   const void* __restrict__ sid_raw,
                                   float* __restrict__ mask_out,
                                   int B, int L, int D, long long NS) {
    int b = blockIdx.x * blockDim.x + threadIdx.x;
    if (b >= B) return;
    const int* sw = (const int*)sid_raw;
    int all0 = 1;
    for (int i = 1; i < B; i += 2)
        if (sw[i] != 0) { all0 = 0; break; }
    long long s = all0 ? ((const long long*)sid_raw)[b] : (long long)sw[b];
    if (s < 0) s = 0;
    if (s >= NS) s = NS - 1;
    int cnt = 0;
    for (int l = 0; l < L; ++l) {
        size_t row = (size_t)b * L + l;
        int m = mask[row];
        int pad = (m == 0);
        int take = pad && (cnt < NPROMPT);
        const float* src = take
            ? prompts + ((size_t)s * NPROMPT + cnt) * (size_t)D
            : in + row * (size_t)D;
        g_src[row] = (unsigned long long)src;
        if (mask_out) mask_out[row] = take ? 1.0f : (float)m;
        cnt += pad;
    }
}

__global__ void copy_scalar_kernel(float* __restrict__ out, int BL, int D) {
    int row = blockIdx.x;
    if (row >= BL) return;
    const float* __restrict__ src = (const float*)g_src[row];
    float* __restrict__ dst = out + (size_t)row * D;
    for (int c = threadIdx.x; c < D; c += blockDim.x) dst[c] = src[c];
}

// ===========================================================================
extern "C" void kernel_launch(void* const* d_in, const int* in_sizes, int n_in,
                              void* d_out, int out_size) {
    // Bind inputs by size rank:
    //   smallest     -> sample_id_tensor [B]
    //   2nd smallest -> attention_mask   [B*L]
    //   2nd largest  -> input_embeds     [B*L*D]
    //   largest      -> prompt_embeddings [NS*NPROMPT*D]
    int idx[4] = {0, 1, 2, 3};
    for (int i = 0; i < 4; ++i)
        for (int j = i + 1; j < 4; ++j)
            if (in_sizes[idx[j]] < in_sizes[idx[i]]) {
                int t = idx[i]; idx[i] = idx[j]; idx[j] = t;
            }
    const void*  sid     = d_in[idx[0]];
    const int*   mask    = (const int*)d_in[idx[1]];
    const float* embeds  = (const float*)d_in[idx[2]];
    const float* prompts = (const float*)d_in[idx[3]];

    int B  = in_sizes[idx[0]];
    int BL = in_sizes[idx[1]];
    int L  = BL / B;
    long long D  = (long long)in_sizes[idx[2]] / BL;
    long long NS = (long long)in_sizes[idx[3]] / (NPROMPT * D);

    float* out = (float*)d_out;
    size_t embed_elems = (size_t)BL * (size_t)D;
    float* mask_out = ((size_t)out_size >= embed_elems + (size_t)BL)
                          ? out + embed_elems
                          : nullptr;

    bool ok_prep = (L <= 1024) && ((L & 3) == 0) && (B <= 4096) && ((D & 3) == 0);

    if (ok_prep) {
        int Dv = (int)(D >> 2);
        int athreads = ((L + 31) / 32) * 32;
        if (athreads < 128) athreads = 128;
        prep_kernel<<<B, athreads, L>>>(mask, sid, mask_out, B, L, NS);

        if (Dv == 192 && (BL & 3) == 0) {
            int npatch = B * NPROMPT;
            int ncopy = BL / 4;
            mega_kernel<192><<<npatch + ncopy, 256>>>(
                (const float4*)embeds, (const float4*)prompts,
                (float4*)out, L, npatch);
        } else {
            size_t n4 = embed_elems >> 2;
            int bthreads = 256;
            int bblocks = (int)((n4 + (size_t)bthreads * 4 - 1) /
                                ((size_t)bthreads * 4));
            flat_copy_kernel<<<bblocks, bthreads>>>(
                (const float4*)embeds, (float4*)out, n4);
            int cthreads = Dv < 1024 ? ((Dv + 31) / 32) * 32 : 1024;
            if (cthreads < 64) cthreads = 64;
            patch_kernel<<<B * NPROMPT, cthreads>>>(
                (const float4*)prompts, (float4*)out, L, Dv);
        }
    } else {
        int threads = 128;
        int blocks = (B + threads - 1) / threads;
        prep_serial_kernel<<<blocks, threads>>>(mask, embeds, prompts, sid,
                                                mask_out, B, (int)L, (int)D, NS);
        int cthreads = (int)(D < 1024 ? ((D + 31) / 32) * 32 : 1024);
        copy_scalar_kernel<<<BL, cthreads>>>(out, BL, (int)D);
    }
}